// round 1
// baseline (speedup 1.0000x reference)
#include <cuda_runtime.h>
#include <cuda_bf16.h>

// PointGNN, algebraically reduced:
//   adj[n,i,j] = |x_i - x_j|^2 < 0.05   (fixed, from original x; diagonal always set)
//   per t: F[n,j]   = MLP_f([0,0,0,state_j])        (per NODE, not per edge)
//          agg[n,i] = max_{j in adj(n,i)} F[n,j]    (channelwise, F >= 0 so floor 0 is exact)
//          state   += relu(MLP_g(agg))
// h-MLP inputs are provably zero in the reference -> entirely dead.

#define NB 4
#define MM 384
#define NODES (NB*MM)
#define MASKW 12   // 384 bits / 32

__device__ unsigned int g_adj[NODES * MASKW];
__device__ float g_F[NODES * 128];
__device__ float g_agg[NODES * 128];

// ---------------------------------------------------------------------------
// Kernel 1: adjacency bitmask + state init (state := x)
// grid = NODES blocks, 384 threads (thread j tests pair (i,j))
// ---------------------------------------------------------------------------
__global__ void adj_init_kernel(const float* __restrict__ x, float* __restrict__ state) {
    int b   = blockIdx.x;            // n*384 + i
    int n   = b / MM;
    int tid = threadIdx.x;           // j
    float xi0 = x[b*3+0], xi1 = x[b*3+1], xi2 = x[b*3+2];
    const float* xj = x + (n*MM + tid)*3;
    float dx = xi0 - xj[0];
    float dy = xi1 - xj[1];
    float dz = xi2 - xj[2];
    // non-contracted to match the reference's (diff*diff).sum() compare
    float s = __fadd_rn(__fadd_rn(__fmul_rn(dx,dx), __fmul_rn(dy,dy)), __fmul_rn(dz,dz));
    unsigned m = __ballot_sync(0xffffffffu, s < 0.05f);
    if ((tid & 31) == 0) g_adj[b*MASKW + (tid >> 5)] = m;
    if (tid < 3) state[b*3 + tid] = x[b*3 + tid];
}

// ---------------------------------------------------------------------------
// Kernel 2: per-node MLP_f  (input = [0,0,0,s0,s1,s2] -> only fW1 rows 3..5)
// 8 nodes per block, 128 threads (thread = output channel), grid = 192
// ---------------------------------------------------------------------------
#define BN 8
__global__ void mlp_f_kernel(const float* __restrict__ state,
                             const float* __restrict__ W1, const float* __restrict__ b1,
                             const float* __restrict__ W2, const float* __restrict__ b2,
                             const float* __restrict__ W3, const float* __restrict__ b3) {
    __shared__ float s_s[BN][3];
    __shared__ float s_h1[BN][64];
    __shared__ float s_h2[BN][128];
    int base = blockIdx.x * BN;
    int tid  = threadIdx.x;          // 0..127

    if (tid < BN*3) s_s[tid/3][tid%3] = state[base*3 + tid];
    __syncthreads();

    // layer1: 6->64 (only rows 3..5 live)
    for (int o = tid; o < BN*64; o += 128) {
        int i = o >> 6, k = o & 63;
        float acc = b1[k];
        acc = fmaf(s_s[i][0], W1[3*64 + k], acc);
        acc = fmaf(s_s[i][1], W1[4*64 + k], acc);
        acc = fmaf(s_s[i][2], W1[5*64 + k], acc);
        s_h1[i][k] = fmaxf(acc, 0.f);
    }
    __syncthreads();

    // layer2: 64->128, channel-per-thread, weight reused across BN nodes
    int c = tid;
    {
        float acc[BN];
        #pragma unroll
        for (int i = 0; i < BN; i++) acc[i] = b2[c];
        #pragma unroll 4
        for (int k = 0; k < 64; k++) {
            float w = W2[k*128 + c];
            #pragma unroll
            for (int i = 0; i < BN; i++) acc[i] = fmaf(s_h1[i][k], w, acc[i]);
        }
        #pragma unroll
        for (int i = 0; i < BN; i++) s_h2[i][c] = fmaxf(acc[i], 0.f);
    }
    __syncthreads();

    // layer3: 128->128 + final relu
    {
        float acc[BN];
        #pragma unroll
        for (int i = 0; i < BN; i++) acc[i] = b3[c];
        #pragma unroll 4
        for (int k = 0; k < 128; k++) {
            float w = W3[k*128 + c];
            #pragma unroll
            for (int i = 0; i < BN; i++) acc[i] = fmaf(s_h2[i][k], w, acc[i]);
        }
        #pragma unroll
        for (int i = 0; i < BN; i++) g_F[(base + i)*128 + c] = fmaxf(acc[i], 0.f);
    }
}

// ---------------------------------------------------------------------------
// Kernel 3: masked channelwise max over neighbors (bit-scan the mask)
// grid = NODES blocks, 128 threads (thread = channel); mask uniform per warp
// ---------------------------------------------------------------------------
__global__ void max_kernel() {
    int b = blockIdx.x;              // n*384 + i
    int n = b / MM;
    int c = threadIdx.x;
    __shared__ unsigned s_mask[MASKW];
    if (c < MASKW) s_mask[c] = g_adj[b*MASKW + c];
    __syncthreads();
    const float* Fn = g_F + n*MM*128;
    float m = 0.f;                   // exact floor: masked entries are 0, F >= 0
    #pragma unroll
    for (int w = 0; w < MASKW; w++) {
        unsigned mk = s_mask[w];
        while (mk) {
            int bit = __ffs(mk) - 1;
            mk &= mk - 1;
            m = fmaxf(m, Fn[(w*32 + bit)*128 + c]);
        }
    }
    g_agg[b*128 + c] = m;
}

// ---------------------------------------------------------------------------
// Kernel 4: per-node MLP_g (128->64->32->3, all relu) + residual into state
// 8 nodes per block, 128 threads, grid = 192
// ---------------------------------------------------------------------------
__global__ void mlp_g_kernel(float* __restrict__ state,
                             const float* __restrict__ W1, const float* __restrict__ b1,
                             const float* __restrict__ W2, const float* __restrict__ b2,
                             const float* __restrict__ W3, const float* __restrict__ b3) {
    __shared__ float s_a[BN][128];
    __shared__ float s_h1[BN][64];
    __shared__ float s_h2[BN][32];
    int base = blockIdx.x * BN;
    int tid  = threadIdx.x;

    for (int o = tid; o < BN*128; o += 128)
        s_a[o >> 7][o & 127] = g_agg[base*128 + o];
    __syncthreads();

    // layer1: 128->64; thread t: k = t%64, node-group t/64 (4 nodes each)
    {
        int k = tid & 63, g = tid >> 6;
        for (int i = g*4; i < g*4 + 4; i++) {
            float acc = b1[k];
            #pragma unroll 4
            for (int d = 0; d < 128; d++)
                acc = fmaf(s_a[i][d], W1[d*64 + k], acc);
            s_h1[i][k] = fmaxf(acc, 0.f);
        }
    }
    __syncthreads();

    // layer2: 64->32; thread t: k = t%32, group t/32 (2 nodes each)
    {
        int k = tid & 31, g = tid >> 5;
        for (int i = g*2; i < g*2 + 2; i++) {
            float acc = b2[k];
            #pragma unroll 4
            for (int d = 0; d < 64; d++)
                acc = fmaf(s_h1[i][d], W2[d*32 + k], acc);
            s_h2[i][k] = fmaxf(acc, 0.f);
        }
    }
    __syncthreads();

    // layer3: 32->3 + relu + residual
    if (tid < BN*3) {
        int i = tid / 3, d = tid % 3;
        float acc = b3[d];
        #pragma unroll
        for (int k = 0; k < 32; k++)
            acc = fmaf(s_h2[i][k], W3[k*3 + d], acc);
        state[(base + i)*3 + d] += fmaxf(acc, 0.f);
    }
}

// ---------------------------------------------------------------------------
// Launch: 1 + 3*(f, max, g) = 10 graph nodes. state lives in d_out.
// Input order: 0=x, 1..6 = h-params (dead), 7..12 = f-params, 13..18 = g-params
// ---------------------------------------------------------------------------
extern "C" void kernel_launch(void* const* d_in, const int* in_sizes, int n_in,
                              void* d_out, int out_size) {
    const float* x   = (const float*)d_in[0];
    const float* fW1 = (const float*)d_in[7];
    const float* fb1 = (const float*)d_in[8];
    const float* fW2 = (const float*)d_in[9];
    const float* fb2 = (const float*)d_in[10];
    const float* fW3 = (const float*)d_in[11];
    const float* fb3 = (const float*)d_in[12];
    const float* gW1 = (const float*)d_in[13];
    const float* gb1 = (const float*)d_in[14];
    const float* gW2 = (const float*)d_in[15];
    const float* gb2 = (const float*)d_in[16];
    const float* gW3 = (const float*)d_in[17];
    const float* gb3 = (const float*)d_in[18];
    float* state = (float*)d_out;

    adj_init_kernel<<<NODES, MM>>>(x, state);
    for (int t = 0; t < 3; t++) {
        mlp_f_kernel<<<NODES/BN, 128>>>(state,
            fW1 + t*6*64,    fb1 + t*64,
            fW2 + t*64*128,  fb2 + t*128,
            fW3 + t*128*128, fb3 + t*128);
        max_kernel<<<NODES, 128>>>();
        mlp_g_kernel<<<NODES/BN, 128>>>(state,
            gW1 + t*128*64, gb1 + t*64,
            gW2 + t*64*32,  gb2 + t*32,
            gW3 + t*32*3,   gb3 + t*3);
    }
}

// round 5
// speedup vs baseline: 1.1398x; 1.1398x over previous
#include <cuda_runtime.h>
#include <cuda_bf16.h>

// PointGNN, algebraically reduced:
//   adj[n,i,j] = |x_i - x_j|^2 < 0.05  (fixed from original x; diagonal in-set)
//   F_t[j]     = MLP_f([0,0,0,state_j])            (per NODE, not per edge)
//   agg_t[i]   = max_{j in adj(i)} F_t[j]          (channelwise; F>=0 so 0-floor exact)
//   state     += relu(MLP_g(agg_t))
// The h-MLP is provably dead (its "relative position" input is identically 0).
//
// Launch plan (4 graph nodes):
//   step<ADJ=1,MAXG=0,DOF=1>  : adjacency bitmask + state:=x + F0 = MLP_f(x)
//   step<0,1,1> (g0,f1)       : max,g (t=0) then F1 = MLP_f(new state)
//   step<0,1,1> (g1,f2)       : max,g (t=1) then F2
//   step<0,1,0> (g2)          : max,g (t=2)

#define MM    384
#define NODES (4*MM)
#define MASKW 12      // 384 bits / 32
#define BN    8       // nodes per block
#define TPB   256

__device__ unsigned g_adj[NODES * MASKW];
__device__ float    g_F[NODES * 128];

// cooperative smem staging, float4
__device__ __forceinline__ void stage(float* dst, const float* src, int nfloats) {
    const float4* s4 = (const float4*)src;
    float4*       d4 = (float4*)dst;
    for (int idx = threadIdx.x; idx < (nfloats >> 2); idx += TPB) d4[idx] = s4[idx];
}

// ---------------------------------------------------------------------------
// fused step: [adj+init | max+MLP_g+residual] then [MLP_f -> g_F]
// grid = NODES/BN = 192, block = 256. Big weight matrices staged in smem.
// ---------------------------------------------------------------------------
template<bool ADJ, bool MAXG, bool DOF>
__global__ __launch_bounds__(TPB) void step_kernel(
    const float* x,
    float* state,
    const float* gW1, const float* gb1,
    const float* gW2, const float* gb2,
    const float* gW3, const float* gb3,
    const float* fW1, const float* fb1,
    const float* fW2, const float* fb2,
    const float* fW3, const float* fb3)
{
    __shared__ float    sW[8192];        // 32KB weight staging (reused per layer)
    __shared__ float    sA[BN][128];
    __shared__ float    sB[BN][128];
    __shared__ unsigned sM[BN][MASKW];

    const int t    = threadIdx.x;
    const int base = blockIdx.x * BN;    // all BN nodes in same batch (384 % 8 == 0)
    const int n    = base / MM;
    const int c    = t & 127;            // channel lane for 128-wide phases
    const int g2   = t >> 7;             // 0/1 -> node quad
    const int k64  = t & 63;             // channel lane for 64-wide phases
    const int q4   = t >> 6;             // 0..3 -> node pair

    if (ADJ) {
        // ---- adjacency bitmask: warp w handles node base+w; lane = neighbor j ----
        const int warp = t >> 5, lane = t & 31;
        const int i    = base + warp;
        float xi0 = x[i*3+0], xi1 = x[i*3+1], xi2 = x[i*3+2];
        #pragma unroll
        for (int wc = 0; wc < MASKW; wc++) {
            const float* xj = x + (n*MM + wc*32 + lane)*3;
            float dx = xi0 - xj[0], dy = xi1 - xj[1], dz = xi2 - xj[2];
            // non-contracted to match the reference's (diff*diff).sum() compare
            float s = __fadd_rn(__fadd_rn(__fmul_rn(dx,dx), __fmul_rn(dy,dy)),
                                __fmul_rn(dz,dz));
            unsigned m = __ballot_sync(0xffffffffu, s < 0.05f);
            if (lane == 0) g_adj[i*MASKW + wc] = m;
        }
        // state := x for our 8 nodes; keep a copy in sB for the f phase
        if (t < BN*3) {
            float v = x[base*3 + t];
            state[base*3 + t] = v;
            sB[t/3][t%3] = v;
        }
        __syncthreads();
    }

    if (MAXG) {
        // ---- masks ----
        if (t < BN*MASKW) sM[t / MASKW][t % MASKW] = g_adj[base*MASKW + t];
        __syncthreads();

        // ---- phase A: channelwise max over adjacency (bit-scan) ----
        const float* Fn = g_F + n*MM*128;
        #pragma unroll
        for (int j = 0; j < 4; j++) {
            int i = g2*4 + j;
            float m = 0.f;                        // exact floor (F >= 0, diag in-set)
            #pragma unroll
            for (int w = 0; w < MASKW; w++) {
                unsigned mk = sM[i][w];
                while (mk) {
                    int bit = __ffs(mk) - 1; mk &= mk - 1;
                    m = fmaxf(m, Fn[(w*32 + bit)*128 + c]);
                }
            }
            sA[i][c] = m;
        }
        __syncthreads();

        // ---- phase B: g layer1 (128 -> 64), weights from smem, ILP-2 ----
        stage(sW, gW1, 128*64);
        __syncthreads();
        {
            float a0 = gb1[k64], a1 = a0;
            const float* A0 = sA[q4*2], * A1 = sA[q4*2 + 1];
            #pragma unroll 8
            for (int d = 0; d < 128; d++) {
                float w = sW[d*64 + k64];
                a0 = fmaf(A0[d], w, a0);
                a1 = fmaf(A1[d], w, a1);
            }
            sB[q4*2    ][k64] = fmaxf(a0, 0.f);
            sB[q4*2 + 1][k64] = fmaxf(a1, 0.f);
        }
        __syncthreads();

        // ---- phase C: g layer2 (64 -> 32) ----
        stage(sW, gW2, 64*32);
        __syncthreads();
        {
            int k2 = t & 31, i8 = t >> 5;        // one node per 32-thread group
            float a = gb2[k2];
            #pragma unroll 8
            for (int d = 0; d < 64; d++) a = fmaf(sB[i8][d], sW[d*32 + k2], a);
            sA[i8][k2] = fmaxf(a, 0.f);
        }
        __syncthreads();

        // ---- phase D: g layer3 (32 -> 3) + relu + residual ----
        if (t < BN*3) {
            int i = t / 3, d = t % 3;
            float acc = gb3[d];
            #pragma unroll
            for (int k3 = 0; k3 < 32; k3++) acc = fmaf(sA[i][k3], gW3[k3*3 + d], acc);
            float ns = state[(base + i)*3 + d] + fmaxf(acc, 0.f);
            state[(base + i)*3 + d] = ns;
            sB[i][d] = ns;                        // new state for the f phase
        }
        __syncthreads();
    }

    if (DOF) {
        // ---- f layer1 (only rows 3..5 of fW1 are live) ----
        #pragma unroll
        for (int j = 0; j < 2; j++) {
            int i = q4*2 + j;
            float acc = fb1[k64];
            acc = fmaf(sB[i][0], fW1[3*64 + k64], acc);
            acc = fmaf(sB[i][1], fW1[4*64 + k64], acc);
            acc = fmaf(sB[i][2], fW1[5*64 + k64], acc);
            sA[i][k64] = fmaxf(acc, 0.f);
        }
        __syncthreads();

        // ---- f layer2 (64 -> 128), ILP-4 ----
        stage(sW, fW2, 64*128);
        __syncthreads();
        float acc2[4];
        #pragma unroll
        for (int j = 0; j < 4; j++) acc2[j] = fb2[c];
        #pragma unroll 4
        for (int kk = 0; kk < 64; kk++) {
            float w = sW[kk*128 + c];
            #pragma unroll
            for (int j = 0; j < 4; j++) acc2[j] = fmaf(sA[g2*4 + j][kk], w, acc2[j]);
        }
        #pragma unroll
        for (int j = 0; j < 4; j++) sB[g2*4 + j][c] = fmaxf(acc2[j], 0.f);
        __syncthreads();

        // ---- f layer3 (128 -> 128) in two 32KB weight halves, ILP-4 ----
        float acc3[4];
        #pragma unroll
        for (int j = 0; j < 4; j++) acc3[j] = fb3[c];

        stage(sW, fW3, 64*128);                  // rows 0..63
        __syncthreads();
        #pragma unroll 4
        for (int kk = 0; kk < 64; kk++) {
            float w = sW[kk*128 + c];
            #pragma unroll
            for (int j = 0; j < 4; j++) acc3[j] = fmaf(sB[g2*4 + j][kk], w, acc3[j]);
        }
        __syncthreads();
        stage(sW, fW3 + 64*128, 64*128);         // rows 64..127
        __syncthreads();
        #pragma unroll 4
        for (int kk = 0; kk < 64; kk++) {
            float w = sW[kk*128 + c];
            #pragma unroll
            for (int j = 0; j < 4; j++) acc3[j] = fmaf(sB[g2*4 + j][64 + kk], w, acc3[j]);
        }
        #pragma unroll
        for (int j = 0; j < 4; j++)
            g_F[(base + g2*4 + j)*128 + c] = fmaxf(acc3[j], 0.f);
    }
}

// ---------------------------------------------------------------------------
extern "C" void kernel_launch(void* const* d_in, const int* in_sizes, int n_in,
                              void* d_out, int out_size) {
    const float* x   = (const float*)d_in[0];
    const float* fW1 = (const float*)d_in[7];
    const float* fb1 = (const float*)d_in[8];
    const float* fW2 = (const float*)d_in[9];
    const float* fb2 = (const float*)d_in[10];
    const float* fW3 = (const float*)d_in[11];
    const float* fb3 = (const float*)d_in[12];
    const float* gW1 = (const float*)d_in[13];
    const float* gb1 = (const float*)d_in[14];
    const float* gW2 = (const float*)d_in[15];
    const float* gb2 = (const float*)d_in[16];
    const float* gW3 = (const float*)d_in[17];
    const float* gb3 = (const float*)d_in[18];
    float* state = (float*)d_out;

    const int SGRID = NODES / BN;   // 192

    // launch 0: adjacency + state init + F0
    step_kernel<true, false, true><<<SGRID, TPB>>>(x, state,
        nullptr, nullptr, nullptr, nullptr, nullptr, nullptr,
        fW1, fb1, fW2, fb2, fW3, fb3);

    // t = 0, 1: max+g then next F
    for (int tt = 0; tt < 2; tt++) {
        step_kernel<false, true, true><<<SGRID, TPB>>>(nullptr, state,
            gW1 + tt*128*64, gb1 + tt*64,
            gW2 + tt*64*32,  gb2 + tt*32,
            gW3 + tt*32*3,   gb3 + tt*3,
            fW1 + (tt+1)*6*64,    fb1 + (tt+1)*64,
            fW2 + (tt+1)*64*128,  fb2 + (tt+1)*128,
            fW3 + (tt+1)*128*128, fb3 + (tt+1)*128);
    }

    // t = 2: max+g only
    step_kernel<false, true, false><<<SGRID, TPB>>>(nullptr, state,
        gW1 + 2*128*64, gb1 + 2*64,
        gW2 + 2*64*32,  gb2 + 2*32,
        gW3 + 2*32*3,   gb3 + 2*3,
        nullptr, nullptr, nullptr, nullptr, nullptr, nullptr);
}

// round 7
// speedup vs baseline: 1.7771x; 1.5592x over previous
#include <cuda_runtime.h>
#include <cuda_bf16.h>

// PointGNN, algebraically reduced:
//   adj(i) = { j : |x_i - x_j|^2 < 0.05 }  (fixed; self always in-set)
//   F_t[j]   = MLP_f([0,0,0,state_j])      (per NODE, not per edge)
//   agg_t[i] = max_{j in adj(i)} F_t[j]    (channelwise; F>=0 so 0-floor exact)
//   state   += relu(MLP_g(agg_t))
// h-MLP is provably dead. Adjacency stored as padded neighbor-index lists
// (padded with self -> duplicates harmless under max).

#define MM    384
#define NODES (4*MM)
#define MASKW 12
#define BN    8
#define TPB   256
#define MAXD  128     // degree cap (mean ~18, max ~40; 128 = huge margin)

__device__ unsigned short g_nbr[NODES * MAXD];
__device__ int            g_deg[NODES];
__device__ float          g_F[NODES * 128];

// cooperative smem staging, float4
__device__ __forceinline__ void stage(float* dst, const float* src, int nfloats) {
    const float4* s4 = (const float4*)src;
    float4*       d4 = (float4*)dst;
    for (int idx = threadIdx.x; idx < (nfloats >> 2); idx += TPB) d4[idx] = s4[idx];
}

// ---------------------------------------------------------------------------
// fused step: [adj-list build + init | max + MLP_g + residual] then [MLP_f]
// grid = NODES/BN = 192, block = 256.
// smem: sW(32KB) + sA(4KB) + sB(4KB) + sN(2KB) + misc = 43.4KB < 48KB
// ---------------------------------------------------------------------------
template<bool ADJ, bool MAXG, bool DOF>
__global__ __launch_bounds__(TPB) void step_kernel(
    const float* x,
    float* state,
    const float* gW1, const float* gb1,
    const float* gW2, const float* gb2,
    const float* gW3, const float* gb3,
    const float* fW1, const float* fb1,
    const float* fW2, const float* fb2,
    const float* fW3, const float* fb3)
{
    __shared__ float          sW[8192];       // gW1 | fW2 | fW3 halves (each exactly 8192)
    __shared__ float          sA[BN][128];
    __shared__ float          sB[BN][128];
    __shared__ unsigned short sN[BN][MAXD];
    __shared__ int            sD[BN];
    __shared__ float          sG3[96];

    const int t    = threadIdx.x;
    const int base = blockIdx.x * BN;        // 8 nodes, all in same batch
    const int n    = base / MM;
    const int c    = t & 127;                // channel lane (128-wide phases)
    const int g2   = t >> 7;                 // node quad selector
    const int k64  = t & 63;
    const int q4   = t >> 6;

    // ---- top-of-kernel prefetches (overlap all small latencies) ----
    float bf1 = 0.f, bf2 = 0.f, bf3 = 0.f;
    if (DOF) { bf1 = fb1[k64]; bf2 = fb2[c]; bf3 = fb3[c]; }
    float bg1 = 0.f, bg2 = 0.f, bg3s = 0.f, stv = 0.f;
    if (MAXG) {
        bg1 = gb1[k64];
        bg2 = gb2[t & 31];
        if (t < 24) { bg3s = gb3[t % 3]; stv = state[base*3 + t]; }
        if (t < 96) sG3[t] = gW3[t];
        if (t < BN) sD[t] = g_deg[base + t];
        // copy 8 neighbor lists (8*128 shorts = 512 uint32)
        const unsigned* src = (const unsigned*)(g_nbr + base*MAXD);
        #pragma unroll
        for (int r = 0; r < 2; r++) ((unsigned*)sN)[t + r*TPB] = src[t + r*TPB];
        // stage gW1 now; its L2 latency overlaps the max phase below
        stage(sW, gW1, 128*64);
    }

    if (ADJ) {
        // ---- warp-per-node neighbor-list build (popc-prefix compaction) ----
        const int warp = t >> 5, lane = t & 31;
        const int i    = base + warp;
        float xi0 = x[i*3+0], xi1 = x[i*3+1], xi2 = x[i*3+2];
        int cnt = 0;
        #pragma unroll
        for (int wc = 0; wc < MASKW; wc++) {
            int j = wc*32 + lane;
            const float* xj = x + (n*MM + j)*3;
            float dx = xi0 - xj[0], dy = xi1 - xj[1], dz = xi2 - xj[2];
            // non-contracted to match reference's (diff*diff).sum() compare
            float s = __fadd_rn(__fadd_rn(__fmul_rn(dx,dx), __fmul_rn(dy,dy)),
                                __fmul_rn(dz,dz));
            bool pred = s < 0.05f;
            unsigned m = __ballot_sync(0xffffffffu, pred);
            int pos = cnt + __popc(m & ((1u << lane) - 1u));
            if (pred && pos < MAXD) g_nbr[i*MAXD + pos] = (unsigned short)j;
            cnt += __popc(m);
        }
        if (lane == 0) {
            int cl = cnt < MAXD ? cnt : MAXD;
            int padded = (cl + 3) & ~3;
            unsigned short self = (unsigned short)(i - n*MM);
            for (int p = cl; p < padded; p++) g_nbr[i*MAXD + p] = self;
            g_deg[i] = padded;
        }
        // state := x; keep copy in sB for the f phase
        if (t < BN*3) {
            float v = x[base*3 + t];
            state[base*3 + t] = v;
            sB[t/3][t%3] = v;
        }
        __syncthreads();
    }

    if (MAXG) {
        __syncthreads();   // sN/sD/sG3 ready; sW (gW1) staged by here

        // ---- phase A: channelwise max, 4 independent loads in flight ----
        const float* Fn = g_F + n*MM*128;
        #pragma unroll
        for (int j = 0; j < 4; j++) {
            int i  = g2*4 + j;
            int dg = sD[i];
            float m = 0.f;
            for (int d = 0; d < dg; d += 4) {
                int j0 = sN[i][d+0], j1 = sN[i][d+1];
                int j2 = sN[i][d+2], j3 = sN[i][d+3];
                float v0 = Fn[j0*128 + c], v1 = Fn[j1*128 + c];
                float v2 = Fn[j2*128 + c], v3 = Fn[j3*128 + c];
                m = fmaxf(m, fmaxf(fmaxf(v0, v1), fmaxf(v2, v3)));
            }
            sA[i][c] = m;
        }
        __syncthreads();

        // ---- phase B: g layer1 (128 -> 64), ILP-2, weights in smem ----
        {
            float a0 = bg1, a1 = bg1;
            const float* A0 = sA[q4*2], * A1 = sA[q4*2 + 1];
            #pragma unroll 8
            for (int d = 0; d < 128; d++) {
                float w = sW[d*64 + k64];
                a0 = fmaf(A0[d], w, a0);
                a1 = fmaf(A1[d], w, a1);
            }
            sB[q4*2    ][k64] = fmaxf(a0, 0.f);
            sB[q4*2 + 1][k64] = fmaxf(a1, 0.f);
        }
        __syncthreads();

        // ---- phase C: g layer2 (64 -> 32), weights direct from L2
        //      (coalesced, fully unrolled -> compiler front-batches loads) ----
        {
            int k2 = t & 31, i8 = t >> 5;
            float a = bg2;
            #pragma unroll
            for (int d = 0; d < 64; d++) a = fmaf(sB[i8][d], gW2[d*32 + k2], a);
            sA[i8][k2] = fmaxf(a, 0.f);
        }
        __syncthreads();

        // ---- phase D: g layer3 (32 -> 3) + relu + residual ----
        if (t < BN*3) {
            int i = t / 3, d = t % 3;
            float acc = bg3s;
            #pragma unroll
            for (int k3 = 0; k3 < 32; k3++) acc = fmaf(sA[i][k3], sG3[k3*3 + d], acc);
            float ns = stv + fmaxf(acc, 0.f);
            state[base*3 + t] = ns;
            sB[i][d] = ns;                       // new state for f phase
        }
        __syncthreads();
    }

    if (DOF) {
        // ---- f layer1 (only rows 3..5 of fW1 live) + stage fW2 concurrently ----
        stage(sW, fW2, 64*128);
        #pragma unroll
        for (int j = 0; j < 2; j++) {
            int i = q4*2 + j;
            float acc = bf1;
            acc = fmaf(sB[i][0], fW1[3*64 + k64], acc);
            acc = fmaf(sB[i][1], fW1[4*64 + k64], acc);
            acc = fmaf(sB[i][2], fW1[5*64 + k64], acc);
            sA[i][k64] = fmaxf(acc, 0.f);
        }
        __syncthreads();

        // ---- f layer2 (64 -> 128), ILP-4 ----
        float acc2[4];
        #pragma unroll
        for (int j = 0; j < 4; j++) acc2[j] = bf2;
        #pragma unroll 4
        for (int kk = 0; kk < 64; kk++) {
            float w = sW[kk*128 + c];
            #pragma unroll
            for (int j = 0; j < 4; j++) acc2[j] = fmaf(sA[g2*4 + j][kk], w, acc2[j]);
        }
        #pragma unroll
        for (int j = 0; j < 4; j++) sB[g2*4 + j][c] = fmaxf(acc2[j], 0.f);
        __syncthreads();

        // ---- f layer3 (128 -> 128) in two halves, ILP-4 ----
        float acc3[4];
        #pragma unroll
        for (int j = 0; j < 4; j++) acc3[j] = bf3;

        stage(sW, fW3, 64*128);                  // rows 0..63
        __syncthreads();
        #pragma unroll 4
        for (int kk = 0; kk < 64; kk++) {
            float w = sW[kk*128 + c];
            #pragma unroll
            for (int j = 0; j < 4; j++) acc3[j] = fmaf(sB[g2*4 + j][kk], w, acc3[j]);
        }
        __syncthreads();
        stage(sW, fW3 + 64*128, 64*128);         // rows 64..127
        __syncthreads();
        #pragma unroll 4
        for (int kk = 0; kk < 64; kk++) {
            float w = sW[kk*128 + c];
            #pragma unroll
            for (int j = 0; j < 4; j++) acc3[j] = fmaf(sB[g2*4 + j][64 + kk], w, acc3[j]);
        }
        #pragma unroll
        for (int j = 0; j < 4; j++)
            g_F[(base + g2*4 + j)*128 + c] = fmaxf(acc3[j], 0.f);
    }
}

// ---------------------------------------------------------------------------
extern "C" void kernel_launch(void* const* d_in, const int* in_sizes, int n_in,
                              void* d_out, int out_size) {
    const float* x   = (const float*)d_in[0];
    const float* fW1 = (const float*)d_in[7];
    const float* fb1 = (const float*)d_in[8];
    const float* fW2 = (const float*)d_in[9];
    const float* fb2 = (const float*)d_in[10];
    const float* fW3 = (const float*)d_in[11];
    const float* fb3 = (const float*)d_in[12];
    const float* gW1 = (const float*)d_in[13];
    const float* gb1 = (const float*)d_in[14];
    const float* gW2 = (const float*)d_in[15];
    const float* gb2 = (const float*)d_in[16];
    const float* gW3 = (const float*)d_in[17];
    const float* gb3 = (const float*)d_in[18];
    float* state = (float*)d_out;

    const int SGRID = NODES / BN;   // 192

    // launch 0: neighbor lists + state init + F0
    step_kernel<true, false, true><<<SGRID, TPB>>>(x, state,
        nullptr, nullptr, nullptr, nullptr, nullptr, nullptr,
        fW1, fb1, fW2, fb2, fW3, fb3);

    // t = 0, 1: max+g then next F
    for (int tt = 0; tt < 2; tt++) {
        step_kernel<false, true, true><<<SGRID, TPB>>>(nullptr, state,
            gW1 + tt*128*64, gb1 + tt*64,
            gW2 + tt*64*32,  gb2 + tt*32,
            gW3 + tt*32*3,   gb3 + tt*3,
            fW1 + (tt+1)*6*64,    fb1 + (tt+1)*64,
            fW2 + (tt+1)*64*128,  fb2 + (tt+1)*128,
            fW3 + (tt+1)*128*128, fb3 + (tt+1)*128);
    }

    // t = 2: max+g only
    step_kernel<false, true, false><<<SGRID, TPB>>>(nullptr, state,
        gW1 + 2*128*64, gb1 + 2*64,
        gW2 + 2*64*32,  gb2 + 2*32,
        gW3 + 2*32*3,   gb3 + 2*3,
        nullptr, nullptr, nullptr, nullptr, nullptr, nullptr);
}

// round 8
// speedup vs baseline: 2.2611x; 1.2723x over previous
#include <cuda_runtime.h>
#include <cuda_bf16.h>

// PointGNN, algebraically reduced, single persistent kernel:
//   adj(i) = { j : |x_i - x_j|^2 < 0.05 }  (fixed; self always in-set)
//   F_t[j]   = MLP_f([0,0,0,state_j])      (per NODE, not per edge)
//   agg_t[i] = max_{j in adj(i)} F_t[j]    (channelwise; F>=0 so 0-floor exact)
//   state   += relu(MLP_g(agg_t))
// h-MLP provably dead. Neighbor lists built once in SMEM (padded with self to
// x8 -> duplicates harmless under max). g_F double-buffered; 3 grid barriers.
// All 192 blocks are co-resident (one wave) so the software barrier is safe.

#define MM    384
#define NODES (4*MM)
#define MASKW 12
#define BN    8
#define TPB   256
#define GRID  (NODES/BN)   // 192
#define MAXD  128

__device__ float    g_Fbuf[2][NODES * 128];
__device__ unsigned g_bar;   // monotonic; +3*GRID per launch

// fixed 8192-float (32KB) cooperative smem staging
__device__ __forceinline__ void stage8k(float* dst, const float* src) {
    const float4* s4 = (const float4*)src;
    float4*       d4 = (float4*)dst;
    #pragma unroll
    for (int r = 0; r < 8; r++) {
        int idx = threadIdx.x + r * TPB;
        d4[idx] = s4[idx];
    }
}

// grid-wide barrier: monotonic ticket counter, wrap-safe compare
__device__ __forceinline__ void grid_bar() {
    __syncthreads();
    if (threadIdx.x == 0) {
        __threadfence();
        unsigned v = atomicAdd(&g_bar, 1u);
        unsigned target = v - (v % (unsigned)GRID) + (unsigned)GRID;
        unsigned cur;
        do {
            asm volatile("ld.acquire.gpu.u32 %0, [%1];" : "=r"(cur) : "l"(&g_bar));
        } while ((int)(cur - target) < 0);
    }
    __syncthreads();
}

// MLP_f for 8 nodes: sB[i][0..2] = state -> Fout[(i)*128+c]; uses sA, sW scratch
__device__ __forceinline__ void f_phase(
    const float* fW1r, float bf1v, float bf2v, float bf3v,
    const float* fW2p, const float* fW3p,
    float (*sA)[128], float (*sB)[128], float* sW,
    float* Fout, int c, int g2, int k64, int q4)
{
    stage8k(sW, fW2p);                       // latency overlaps layer1
    // layer1: only rows 3..5 of fW1 are live
    #pragma unroll
    for (int j = 0; j < 2; j++) {
        int i = q4*2 + j;
        float acc = bf1v;
        acc = fmaf(sB[i][0], fW1r[3*64 + k64], acc);
        acc = fmaf(sB[i][1], fW1r[4*64 + k64], acc);
        acc = fmaf(sB[i][2], fW1r[5*64 + k64], acc);
        sA[i][k64] = fmaxf(acc, 0.f);
    }
    __syncthreads();

    // layer2: 64 -> 128, ILP-4
    float acc2[4];
    #pragma unroll
    for (int j = 0; j < 4; j++) acc2[j] = bf2v;
    #pragma unroll 4
    for (int kk = 0; kk < 64; kk++) {
        float w = sW[kk*128 + c];
        #pragma unroll
        for (int j = 0; j < 4; j++) acc2[j] = fmaf(sA[g2*4 + j][kk], w, acc2[j]);
    }
    #pragma unroll
    for (int j = 0; j < 4; j++) sB[g2*4 + j][c] = fmaxf(acc2[j], 0.f);
    __syncthreads();

    // layer3: 128 -> 128 in two 32KB halves, ILP-4
    float acc3[4];
    #pragma unroll
    for (int j = 0; j < 4; j++) acc3[j] = bf3v;

    stage8k(sW, fW3p);
    __syncthreads();
    #pragma unroll 4
    for (int kk = 0; kk < 64; kk++) {
        float w = sW[kk*128 + c];
        #pragma unroll
        for (int j = 0; j < 4; j++) acc3[j] = fmaf(sB[g2*4 + j][kk], w, acc3[j]);
    }
    __syncthreads();
    stage8k(sW, fW3p + 8192);
    __syncthreads();
    #pragma unroll 4
    for (int kk = 0; kk < 64; kk++) {
        float w = sW[kk*128 + c];
        #pragma unroll
        for (int j = 0; j < 4; j++) acc3[j] = fmaf(sB[g2*4 + j][64 + kk], w, acc3[j]);
    }
    #pragma unroll
    for (int j = 0; j < 4; j++)
        Fout[(g2*4 + j)*128 + c] = fmaxf(acc3[j], 0.f);
}

// ---------------------------------------------------------------------------
__global__ __launch_bounds__(TPB) void pointgnn_persistent(
    const float* x, float* state,
    const float* fW1, const float* fb1, const float* fW2, const float* fb2,
    const float* fW3, const float* fb3,
    const float* gW1, const float* gb1, const float* gW2, const float* gb2,
    const float* gW3, const float* gb3)
{
    __shared__ float          sW[8192];
    __shared__ float          sA[BN][128];
    __shared__ float          sB[BN][128];
    __shared__ unsigned short sN[BN][MAXD];
    __shared__ int            sD[BN];
    __shared__ float          sG3[3][96];

    const int t    = threadIdx.x;
    const int base = blockIdx.x * BN;
    const int n    = base / MM;
    const int c    = t & 127;
    const int g2   = t >> 7;
    const int k64  = t & 63;
    const int q4   = t >> 6;

    // ---- one-time prefetch: all 3 steps' biases + gW3 + state ----
    float bf1[3], bf2[3], bf3[3], bg1[3], bg2[3], bg3s[3];
    #pragma unroll
    for (int s = 0; s < 3; s++) {
        bf1[s] = fb1[s*64  + k64];
        bf2[s] = fb2[s*128 + c];
        bf3[s] = fb3[s*128 + c];
        bg1[s] = gb1[s*64  + k64];
        bg2[s] = gb2[s*32  + (t & 31)];
    }
    float stv = 0.f;
    if (t < 24) {
        stv = x[base*3 + t];
        #pragma unroll
        for (int s = 0; s < 3; s++) bg3s[s] = gb3[s*3 + t % 3];
    }
    if (t < 96) {
        #pragma unroll
        for (int s = 0; s < 3; s++) sG3[s][t] = gW3[s*96 + t];
    }

    // ---- adjacency (once, pure smem): warp-per-node popc compaction ----
    {
        const int warp = t >> 5, lane = t & 31;
        const int i = base + warp;
        float xi0 = x[i*3+0], xi1 = x[i*3+1], xi2 = x[i*3+2];
        int cnt = 0;
        #pragma unroll
        for (int wc = 0; wc < MASKW; wc++) {
            int j = wc*32 + lane;
            const float* xj = x + (n*MM + j)*3;
            float dx = xi0 - xj[0], dy = xi1 - xj[1], dz = xi2 - xj[2];
            // non-contracted to match reference's (diff*diff).sum() compare
            float s2 = __fadd_rn(__fadd_rn(__fmul_rn(dx,dx), __fmul_rn(dy,dy)),
                                 __fmul_rn(dz,dz));
            bool pred = s2 < 0.05f;
            unsigned m = __ballot_sync(0xffffffffu, pred);
            int pos = cnt + __popc(m & ((1u << lane) - 1u));
            if (pred && pos < MAXD) sN[warp][pos] = (unsigned short)j;
            cnt += __popc(m);
        }
        if (lane == 0) {
            int cl = cnt < MAXD ? cnt : MAXD;
            int padded = (cl + 7) & ~7;            // pad to x8 for ILP-8 max
            unsigned short self = (unsigned short)(i - n*MM);
            for (int p = cl; p < padded; p++) sN[warp][p] = self;
            sD[warp] = padded;
        }
    }
    if (t < 24) sB[t/3][t%3] = stv;                // state := x
    __syncthreads();

    // ---- F0 = MLP_f(x) ----
    f_phase(fW1, bf1[0], bf2[0], bf3[0], fW2, fW3,
            sA, sB, sW, g_Fbuf[0] + base*128, c, g2, k64, q4);
    grid_bar();

    // ---- 3 timesteps ----
    int cur = 0;
    #pragma unroll
    for (int s = 0; s < 3; s++) {
        stage8k(sW, gW1 + s*8192);                 // overlaps max phase below

        // phase A: channelwise max over neighbors, 8 loads in flight
        const float* Fn = g_Fbuf[cur] + n*MM*128;
        #pragma unroll
        for (int j = 0; j < 4; j++) {
            int i  = g2*4 + j;
            int dg = sD[i];
            float m = 0.f;
            for (int d = 0; d < dg; d += 8) {
                float v0 = Fn[sN[i][d+0]*128 + c], v1 = Fn[sN[i][d+1]*128 + c];
                float v2 = Fn[sN[i][d+2]*128 + c], v3 = Fn[sN[i][d+3]*128 + c];
                float v4 = Fn[sN[i][d+4]*128 + c], v5 = Fn[sN[i][d+5]*128 + c];
                float v6 = Fn[sN[i][d+6]*128 + c], v7 = Fn[sN[i][d+7]*128 + c];
                float m01 = fmaxf(v0, v1), m23 = fmaxf(v2, v3);
                float m45 = fmaxf(v4, v5), m67 = fmaxf(v6, v7);
                m = fmaxf(m, fmaxf(fmaxf(m01, m23), fmaxf(m45, m67)));
            }
            sA[i][c] = m;
        }
        __syncthreads();   // also guarantees gW1 staging complete

        // phase B: g layer1 (128 -> 64), ILP-2, weights in smem
        {
            float a0 = bg1[s], a1 = bg1[s];
            const float* A0 = sA[q4*2], * A1 = sA[q4*2 + 1];
            #pragma unroll 8
            for (int d = 0; d < 128; d++) {
                float w = sW[d*64 + k64];
                a0 = fmaf(A0[d], w, a0);
                a1 = fmaf(A1[d], w, a1);
            }
            sB[q4*2    ][k64] = fmaxf(a0, 0.f);
            sB[q4*2 + 1][k64] = fmaxf(a1, 0.f);
        }
        __syncthreads();

        // phase C: g layer2 (64 -> 32), weights direct from L2 (front-batched)
        {
            int k2 = t & 31, i8 = t >> 5;
            const float* W2p = gW2 + s*2048;
            float a = bg2[s];
            #pragma unroll
            for (int d = 0; d < 64; d++) a = fmaf(sB[i8][d], W2p[d*32 + k2], a);
            sA[i8][k2] = fmaxf(a, 0.f);
        }
        __syncthreads();

        // phase D: g layer3 (32 -> 3) + relu + residual (state in regs)
        if (t < 24) {
            int i = t / 3, d = t % 3;
            float acc = bg3s[s];
            #pragma unroll
            for (int k3 = 0; k3 < 32; k3++)
                acc = fmaf(sA[i][k3], sG3[s][k3*3 + d], acc);
            float ns = stv + fmaxf(acc, 0.f);
            stv = ns;
            if (s == 2) state[base*3 + t] = ns;    // final output, once
            else        sB[i][d] = ns;             // feed next f phase
        }
        __syncthreads();

        if (s < 2) {
            f_phase(fW1 + (s+1)*384, bf1[s+1], bf2[s+1], bf3[s+1],
                    fW2 + (s+1)*8192, fW3 + (s+1)*16384,
                    sA, sB, sW, g_Fbuf[cur ^ 1] + base*128, c, g2, k64, q4);
            grid_bar();
            cur ^= 1;
        }
    }
}

// ---------------------------------------------------------------------------
extern "C" void kernel_launch(void* const* d_in, const int* in_sizes, int n_in,
                              void* d_out, int out_size) {
    const float* x   = (const float*)d_in[0];
    const float* fW1 = (const float*)d_in[7];
    const float* fb1 = (const float*)d_in[8];
    const float* fW2 = (const float*)d_in[9];
    const float* fb2 = (const float*)d_in[10];
    const float* fW3 = (const float*)d_in[11];
    const float* fb3 = (const float*)d_in[12];
    const float* gW1 = (const float*)d_in[13];
    const float* gb1 = (const float*)d_in[14];
    const float* gW2 = (const float*)d_in[15];
    const float* gb2 = (const float*)d_in[16];
    const float* gW3 = (const float*)d_in[17];
    const float* gb3 = (const float*)d_in[18];
    float* state = (float*)d_out;

    pointgnn_persistent<<<GRID, TPB>>>(x, state,
        fW1, fb1, fW2, fb2, fW3, fb3,
        gW1, gb1, gW2, gb2, gW3, gb3);
}